// round 7
// baseline (speedup 1.0000x reference)
#include <cuda_runtime.h>

#define BB 2048
#define TT 512
#define VOCAB 4
#define EE 64
#define HH 128
#define G3 384        // 3*H
#define MTILE 16
#define NBLK (BB/MTILE)   // 128 CTAs
#define NTHR 512          // 2 m-groups x 128 j x 2 k-halves

// ---- scratch (no allocs allowed) ----
__device__ float         g_gi[VOCAB * G3];
__device__ unsigned char g_tok[TT * BB];
__device__ int           g_is64;

// ---- smem layout (bytes) ----
#define OFF_W    0                      // 384*128 f32 swizzled   = 196608
#define OFF_H0   196608                 // 16*128 f32 h buf 0     =   8192
#define OFF_H1   204800                 // 16*128 f32 h buf 1     =   8192
#define OFF_GI   212992                 // 4*384 f32              =   6144
#define OFF_TOK  219136                 // 2 groups x 2 bufs x 8  =     32
#define SMEM_BYTES 219168

// packed fp32x2 FMA (Blackwell)
__device__ __forceinline__ unsigned long long fma2(unsigned long long a,
                                                   unsigned long long b,
                                                   unsigned long long c) {
    unsigned long long d;
    asm("fma.rn.f32x2 %0, %1, %2, %3;" : "=l"(d) : "l"(a), "l"(b), "l"(c));
    return d;
}
__device__ __forceinline__ float reduce2(unsigned long long a) {
    unsigned int lo, hi;
    asm("mov.b64 {%0, %1}, %2;" : "=r"(lo), "=r"(hi) : "l"(a));
    return __uint_as_float(lo) + __uint_as_float(hi);
}
__device__ __forceinline__ float tanh_fast(float x) {
    float y;
    asm("tanh.approx.f32 %0, %1;" : "=f"(y) : "f"(x));
    return y;
}
__device__ __forceinline__ float sigmoid_fast(float x) {
    return fmaf(tanh_fast(0.5f * x), 0.5f, 0.5f);
}
// group barrier: 256 threads (8 aligned warps) of m-group mg
__device__ __forceinline__ void group_bar(int mg) {
    asm volatile("bar.sync %0, 256;" :: "r"(mg + 1) : "memory");
}

__global__ void detect_kernel(const int* __restrict__ x32) {
    int all_zero = 1;
    for (int i = 1; i < 128; i += 2) all_zero &= (x32[i] == 0);
    g_is64 = all_zero;
}

__global__ void tok_kernel(const void* __restrict__ xraw) {
    int i = blockIdx.x * blockDim.x + threadIdx.x;
    if (i >= BB * TT) return;
    int b = i / TT, t = i % TT;
    int v;
    if (g_is64) v = (int)((const long long*)xraw)[i];
    else        v = ((const int*)xraw)[i];
    g_tok[t * BB + b] = (unsigned char)v;
}

__global__ void gi_kernel(const float* __restrict__ W_ih,
                          const float* __restrict__ emb,
                          const float* __restrict__ b_ih) {
    int g = threadIdx.x;
    if (g >= G3) return;
    float bi = b_ih[g];
    for (int v = 0; v < VOCAB; ++v) {
        float s = bi;
#pragma unroll 8
        for (int e = 0; e < EE; ++e) s += W_ih[g * EE + e] * emb[v * EE + e];
        g_gi[v * G3 + g] = s;
    }
}

extern __shared__ char smem[];

__global__ __launch_bounds__(NTHR, 1)
void gru_kernel(const float* __restrict__ W_hh, const float* __restrict__ b_hh,
                const float* __restrict__ W_fc, const float* __restrict__ b_fc,
                float* __restrict__ out) {
    float*         h0_s  = (float*)(smem + OFF_H0);
    float*         h1_s  = (float*)(smem + OFF_H1);
    float*         gi_s  = (float*)(smem + OFF_GI);
    unsigned char* tok_s = (unsigned char*)(smem + OFF_TOK);

    const int tid  = threadIdx.x;     // 0..511
    const int w    = tid >> 5;        // warp 0..15
    const int lane = tid & 31;
    const int mg   = w >> 3;          // m-group: rows 8*mg..8*mg+7
    const int wl   = w & 7;           // warp within group
    const int kh   = lane >> 4;       // k-half: even (0) / odd (1) granules
    const int jo   = lane & 15;
    const int j    = wl * 16 + jo;    // hidden unit 0..127
    const int m0   = mg * 8;
    const int me0  = kh * 4;          // first epilogue row within group
    const int row0 = blockIdx.x * MTILE;

    // W_hh -> smem, XOR-swizzled on 16B granules (row r granule c at c^(r&7))
    {
        float4* W_s4 = (float4*)(smem + OFF_W);
        for (int r = tid; r < G3; r += NTHR) {
            const float4* Wg = (const float4*)(W_hh + r * HH);
            int swr = r & 7;
#pragma unroll 4
            for (int c = 0; c < 32; ++c) W_s4[r * 32 + (c ^ swr)] = Wg[c];
        }
    }
    for (int i = tid; i < VOCAB * G3; i += NTHR) gi_s[i] = g_gi[i];
    for (int i = tid; i < MTILE * HH; i += NTHR) h0_s[i] = 0.0f;
    if (wl == 0 && lane < 8) tok_s[mg * 16 + lane] = g_tok[0 * BB + row0 + m0 + lane];

    const unsigned long long bR = (unsigned long long)__float_as_uint(b_hh[j]);
    const unsigned long long bZ = (unsigned long long)__float_as_uint(b_hh[128 + j]);
    const unsigned long long bN = (unsigned long long)__float_as_uint(b_hh[256 + j]);
    __syncthreads();

    const int sw = j & 7;   // (j+128)&7 == (j+256)&7 == j&7
    const ulonglong2* Wr = (const ulonglong2*)(smem + OFF_W) + (j)       * 32;
    const ulonglong2* Wz = (const ulonglong2*)(smem + OFF_W) + (128 + j) * 32;
    const ulonglong2* Wn = (const ulonglong2*)(smem + OFF_W) + (256 + j) * 32;

#define GIDX(c) ((((c) * 2 + kh)) ^ sw)

    for (int t = 0; t < TT; ++t) {
        const int cur = t & 1;
        float* h_cur = cur ? h1_s : h0_s;
        float* h_nxt = cur ? h0_s : h1_s;
        const ulonglong2* hc2 = (const ulonglong2*)h_cur;

        // prefetch old-h for this thread's 4 epilogue rows
        float ho[4];
#pragma unroll
        for (int i = 0; i < 4; ++i) ho[i] = h_cur[(m0 + me0 + i) * HH + j];

        // prefetch next step's tokens for this group's rows
        unsigned char nt = 0;
        if (wl == 0 && lane < 8 && t + 1 < TT)
            nt = g_tok[(t + 1) * BB + row0 + m0 + lane];

        // ---- partial gh over this thread's k-parity, all 3 gates, 8 rows ----
        // bias folded into kh=0 partial only (kh=1 starts at 0)
        unsigned long long aR[8], aZ[8], aN[8];
#pragma unroll
        for (int m = 0; m < 8; ++m) {
            aR[m] = kh ? 0ull : bR; aZ[m] = kh ? 0ull : bZ; aN[m] = kh ? 0ull : bN;
        }

        // depth-1 software pipeline on the W granules
        ulonglong2 wr = Wr[GIDX(0)], wz = Wz[GIDX(0)], wn = Wn[GIDX(0)];
#pragma unroll 4
        for (int c = 0; c < 16; ++c) {
            const int cn = GIDX((c + 1) & 15);
            ulonglong2 wr_n = Wr[cn];
            ulonglong2 wz_n = Wz[cn];
            ulonglong2 wn_n = Wn[cn];
#pragma unroll
            for (int m = 0; m < 8; ++m) {
                ulonglong2 hv = hc2[(m0 + m) * 32 + c * 2 + kh];  // dual broadcast
                aR[m] = fma2(hv.x, wr.x, aR[m]);
                aR[m] = fma2(hv.y, wr.y, aR[m]);
                aZ[m] = fma2(hv.x, wz.x, aZ[m]);
                aZ[m] = fma2(hv.y, wz.y, aZ[m]);
                aN[m] = fma2(hv.x, wn.x, aN[m]);
                aN[m] = fma2(hv.y, wn.y, aN[m]);
            }
            wr = wr_n; wz = wz_n; wn = wn_n;
        }

        // ---- combine k-halves across the lane pair (xor 16) ----
        float sR[8], sZ[8], sN[8];
#pragma unroll
        for (int m = 0; m < 8; ++m) {
            float pR = reduce2(aR[m]);
            float pZ = reduce2(aZ[m]);
            float pN = reduce2(aN[m]);
            sR[m] = pR + __shfl_xor_sync(0xffffffffu, pR, 16);
            sZ[m] = pZ + __shfl_xor_sync(0xffffffffu, pZ, 16);
            sN[m] = pN + __shfl_xor_sync(0xffffffffu, pN, 16);
        }

        // ---- gates + h update for this thread's 4 rows ----
#pragma unroll
        for (int i = 0; i < 4; ++i) {
            int   mi = me0 + i;              // row within group (0..7)
            int   v  = tok_s[mg * 16 + cur * 8 + mi];
            const float* gv = gi_s + v * G3;
            float r  = sigmoid_fast(gv[j]       + sR[mi]);
            float z  = sigmoid_fast(gv[128 + j] + sZ[mi]);
            float n  = tanh_fast   (gv[256 + j] + r * sN[mi]);
            h_nxt[(m0 + mi) * HH + j] = fmaf(z, ho[i] - n, n);  // (1-z)n + z*ho
        }
        if (wl == 0 && lane < 8) tok_s[mg * 16 + (cur ^ 1) * 8 + lane] = nt;
        group_bar(mg);
    }

    __syncthreads();   // join groups: logits read all 16 rows

    // ---- logits = hT @ W_fc.T + b_fc  (final h in buffer 0: TT even) ----
    if (tid < MTILE * VOCAB) {
        int m = tid >> 2, v = tid & 3;
        float        sum = b_fc[v];
        const float* wv  = W_fc + v * HH;
        const float* hr  = h0_s + m * HH;
#pragma unroll 8
        for (int k = 0; k < HH; ++k) sum = fmaf(hr[k], wv[k], sum);
        out[(row0 + m) * VOCAB + v] = sum;
    }
}

extern "C" void kernel_launch(void* const* d_in, const int* in_sizes, int n_in,
                              void* d_out, int out_size) {
    const void*  x    = d_in[0];
    const float* emb  = (const float*)d_in[1];
    const float* W_ih = (const float*)d_in[2];
    const float* W_hh = (const float*)d_in[3];
    const float* b_ih = (const float*)d_in[4];
    const float* b_hh = (const float*)d_in[5];
    const float* W_fc = (const float*)d_in[6];
    const float* b_fc = (const float*)d_in[7];
    float* out = (float*)d_out;

    static int smem_set = 0;
    if (!smem_set) {
        cudaFuncSetAttribute(gru_kernel,
                             cudaFuncAttributeMaxDynamicSharedMemorySize,
                             SMEM_BYTES);
        smem_set = 1;
    }

    detect_kernel<<<1, 1>>>((const int*)x);
    tok_kernel<<<(BB * TT + 255) / 256, 256>>>(x);
    gi_kernel<<<1, G3>>>(W_ih, emb, b_ih);
    gru_kernel<<<NBLK, NTHR, SMEM_BYTES>>>(W_hh, b_hh, W_fc, b_fc, out);
}

// round 8
// speedup vs baseline: 1.1516x; 1.1516x over previous
#include <cuda_runtime.h>

#define BB 2048
#define TT 512
#define VOCAB 4
#define EE 64
#define HH 128
#define G3 384        // 3*H
#define NBLK 148          // one CTA per SM
#define MROWS 14          // rows per CTA (148*14 = 2072 >= 2048, padded)
#define GR 7              // rows per m-group
#define BPAD (NBLK * MROWS)   // 2072 padded batch
#define NTHR 256          // 128 units x 2 m-groups of 7 rows

// ---- scratch (no allocs allowed) ----
__device__ float         g_gi[VOCAB * G3];
__device__ unsigned char g_tok[TT * BPAD];   // zero-init => pad rows read v=0
__device__ int           g_is64;

// ---- smem layout (bytes) ----
#define OFF_W    0                      // 384*128 f32 swizzled   = 196608
#define OFF_H0   196608                 // 14*128 f32 h buf 0     =   7168
#define OFF_H1   203776                 // 14*128 f32 h buf 1     =   7168
#define OFF_GI   210944                 // 4*384 f32              =   6144
#define OFF_TOK  217088                 // 2 groups x 2 bufs x 8  =     32
#define SMEM_BYTES 217120

// packed fp32x2 FMA (Blackwell)
__device__ __forceinline__ unsigned long long fma2(unsigned long long a,
                                                   unsigned long long b,
                                                   unsigned long long c) {
    unsigned long long d;
    asm("fma.rn.f32x2 %0, %1, %2, %3;" : "=l"(d) : "l"(a), "l"(b), "l"(c));
    return d;
}
__device__ __forceinline__ float reduce2(unsigned long long a) {
    unsigned int lo, hi;
    asm("mov.b64 {%0, %1}, %2;" : "=r"(lo), "=r"(hi) : "l"(a));
    return __uint_as_float(lo) + __uint_as_float(hi);
}
__device__ __forceinline__ float tanh_fast(float x) {
    float y;
    asm("tanh.approx.f32 %0, %1;" : "=f"(y) : "f"(x));
    return y;
}
__device__ __forceinline__ float sigmoid_fast(float x) {
    return fmaf(tanh_fast(0.5f * x), 0.5f, 0.5f);
}
// group barrier: 128 threads (4 aligned warps) of m-group mg
__device__ __forceinline__ void group_bar(int mg) {
    asm volatile("bar.sync %0, 128;" :: "r"(mg + 1) : "memory");
}

__global__ void detect_kernel(const int* __restrict__ x32) {
    int all_zero = 1;
    for (int i = 1; i < 128; i += 2) all_zero &= (x32[i] == 0);
    g_is64 = all_zero;
}

__global__ void tok_kernel(const void* __restrict__ xraw) {
    int i = blockIdx.x * blockDim.x + threadIdx.x;
    if (i >= BB * TT) return;
    int b = i / TT, t = i % TT;
    int v;
    if (g_is64) v = (int)((const long long*)xraw)[i];
    else        v = ((const int*)xraw)[i];
    g_tok[t * BPAD + b] = (unsigned char)v;
}

__global__ void gi_kernel(const float* __restrict__ W_ih,
                          const float* __restrict__ emb,
                          const float* __restrict__ b_ih) {
    int g = threadIdx.x;
    if (g >= G3) return;
    float bi = b_ih[g];
    for (int v = 0; v < VOCAB; ++v) {
        float s = bi;
#pragma unroll 8
        for (int e = 0; e < EE; ++e) s += W_ih[g * EE + e] * emb[v * EE + e];
        g_gi[v * G3 + g] = s;
    }
}

extern __shared__ char smem[];

__global__ __launch_bounds__(NTHR, 1)
void gru_kernel(const float* __restrict__ W_hh, const float* __restrict__ b_hh,
                const float* __restrict__ W_fc, const float* __restrict__ b_fc,
                float* __restrict__ out) {
    float*         h0_s  = (float*)(smem + OFF_H0);
    float*         h1_s  = (float*)(smem + OFF_H1);
    float*         gi_s  = (float*)(smem + OFF_GI);
    unsigned char* tok_s = (unsigned char*)(smem + OFF_TOK);

    const int tid  = threadIdx.x;     // 0..255
    const int j    = tid & 127;       // hidden unit
    const int mg   = tid >> 7;        // m-group: rows GR*mg .. GR*mg+GR-1
    const int m0   = mg * GR;
    const int row0 = blockIdx.x * MROWS;

    // W_hh -> smem, XOR-swizzled on 16B granules (row r granule c at c^(r&7))
    {
        float4* W_s4 = (float4*)(smem + OFF_W);
        for (int r = tid; r < G3; r += NTHR) {
            const float4* Wg = (const float4*)(W_hh + r * HH);
            int swr = r & 7;
#pragma unroll 4
            for (int c = 0; c < 32; ++c) W_s4[r * 32 + (c ^ swr)] = Wg[c];
        }
    }
    for (int i = tid; i < VOCAB * G3; i += NTHR) gi_s[i] = g_gi[i];
    for (int i = tid; i < MROWS * HH; i += NTHR) h0_s[i] = 0.0f;
    // group-local token staging: lane j<GR of group mg owns row m0+j
    if (j < GR) tok_s[mg * 16 + j] = g_tok[0 * BPAD + row0 + m0 + j] & 3;

    const unsigned long long bR = (unsigned long long)__float_as_uint(b_hh[j]);
    const unsigned long long bZ = (unsigned long long)__float_as_uint(b_hh[128 + j]);
    const unsigned long long bN = (unsigned long long)__float_as_uint(b_hh[256 + j]);
    __syncthreads();

    const int sw = j & 7;   // (j+128)&7 == (j+256)&7 == j&7
    const ulonglong2* Wr = (const ulonglong2*)(smem + OFF_W) + (j)       * 32;
    const ulonglong2* Wz = (const ulonglong2*)(smem + OFF_W) + (128 + j) * 32;
    const ulonglong2* Wn = (const ulonglong2*)(smem + OFF_W) + (256 + j) * 32;

    // old-h carried in registers: hreg[m] == h_cur[(m0+m)*HH + j]
    float hreg[GR];
#pragma unroll
    for (int m = 0; m < GR; ++m) hreg[m] = 0.0f;

    for (int t = 0; t < TT; ++t) {
        const int cur = t & 1;
        float* h_cur = cur ? h1_s : h0_s;
        float* h_nxt = cur ? h0_s : h1_s;
        const ulonglong2* hc2 = (const ulonglong2*)h_cur;

        // prefetch next step's tokens for this group's rows
        unsigned char nt = 0;
        if (j < GR && t + 1 < TT)
            nt = g_tok[(t + 1) * BPAD + row0 + m0 + j] & 3;

        // ---- gh = b_hh + h @ W_hh^T for all 3 gates of unit j, GR rows ----
        unsigned long long aR[GR], aZ[GR], aN[GR];
#pragma unroll
        for (int m = 0; m < GR; ++m) { aR[m] = bR; aZ[m] = bZ; aN[m] = bN; }

        // depth-1 software pipeline on the W granules (branch-free wrap)
        ulonglong2 wr = Wr[sw], wz = Wz[sw], wn = Wn[sw];
#pragma unroll 4
        for (int c = 0; c < 32; ++c) {
            const int cn = ((c + 1) & 31) ^ sw;
            ulonglong2 wr_n = Wr[cn];
            ulonglong2 wz_n = Wz[cn];
            ulonglong2 wn_n = Wn[cn];
#pragma unroll
            for (int m = 0; m < GR; ++m) {
                ulonglong2 hv = hc2[(m0 + m) * 32 + c];   // warp-broadcast
                aR[m] = fma2(hv.x, wr.x, aR[m]);
                aR[m] = fma2(hv.y, wr.y, aR[m]);
                aZ[m] = fma2(hv.x, wz.x, aZ[m]);
                aZ[m] = fma2(hv.y, wz.y, aZ[m]);
                aN[m] = fma2(hv.x, wn.x, aN[m]);
                aN[m] = fma2(hv.y, wn.y, aN[m]);
            }
            wr = wr_n; wz = wz_n; wn = wn_n;
        }

        // ---- gates + h update, all thread-local ----
        float sR[GR], sZ[GR], sN[GR];
#pragma unroll
        for (int m = 0; m < GR; ++m) {
            sR[m] = reduce2(aR[m]);
            sZ[m] = reduce2(aZ[m]);
            sN[m] = reduce2(aN[m]);
        }
#pragma unroll
        for (int m = 0; m < GR; ++m) {
            int   v  = tok_s[mg * 16 + cur * 8 + m];
            const float* gv = gi_s + v * G3;
            float r  = sigmoid_fast(gv[j]       + sR[m]);
            float z  = sigmoid_fast(gv[128 + j] + sZ[m]);
            float n  = tanh_fast   (gv[256 + j] + r * sN[m]);
            float hn = fmaf(z, hreg[m] - n, n);           // (1-z)n + z*ho
            hreg[m]  = hn;
            h_nxt[(m0 + m) * HH + j] = hn;
        }
        if (j < GR) tok_s[mg * 16 + (cur ^ 1) * 8 + j] = nt;
        group_bar(mg);
    }

    __syncthreads();   // join groups: logits read all MROWS rows

    // ---- logits = hT @ W_fc.T + b_fc  (final h in buffer 0: TT even) ----
    if (tid < MROWS * VOCAB) {
        int m = tid >> 2, v = tid & 3;
        int row = row0 + m;
        if (row < BB) {
            float        sum = b_fc[v];
            const float* wv  = W_fc + v * HH;
            const float* hr  = h0_s + m * HH;
#pragma unroll 8
            for (int k = 0; k < HH; ++k) sum = fmaf(hr[k], wv[k], sum);
            out[row * VOCAB + v] = sum;
        }
    }
}

extern "C" void kernel_launch(void* const* d_in, const int* in_sizes, int n_in,
                              void* d_out, int out_size) {
    const void*  x    = d_in[0];
    const float* emb  = (const float*)d_in[1];
    const float* W_ih = (const float*)d_in[2];
    const float* W_hh = (const float*)d_in[3];
    const float* b_ih = (const float*)d_in[4];
    const float* b_hh = (const float*)d_in[5];
    const float* W_fc = (const float*)d_in[6];
    const float* b_fc = (const float*)d_in[7];
    float* out = (float*)d_out;

    static int smem_set = 0;
    if (!smem_set) {
        cudaFuncSetAttribute(gru_kernel,
                             cudaFuncAttributeMaxDynamicSharedMemorySize,
                             SMEM_BYTES);
        smem_set = 1;
    }

    detect_kernel<<<1, 1>>>((const int*)x);
    tok_kernel<<<(BB * TT + 255) / 256, 256>>>(x);
    gi_kernel<<<1, G3>>>(W_ih, emb, b_ih);
    gru_kernel<<<NBLK, NTHR, SMEM_BYTES>>>(W_hh, b_hh, W_fc, b_fc, out);
}

// round 9
// speedup vs baseline: 1.4049x; 1.2199x over previous
#include <cuda_runtime.h>

#define BB 2048
#define TT 512
#define VOCAB 4
#define EE 64
#define HH 128
#define G3 384        // 3*H
#define NBLK 148          // one CTA per SM
#define MROWS 14          // rows per CTA (148*14 = 2072 >= 2048, padded)
#define GR 7              // rows per m-group
#define BPAD (NBLK * MROWS)   // 2072 padded batch
#define NTHR 256          // 128 units x 2 m-groups of 7 rows

// ---- scratch (no allocs allowed) ----
__device__ float         g_gi[VOCAB * G3];
__device__ unsigned char g_tok[TT * BPAD];   // zero-init => pad rows read v=0
__device__ int           g_is64;

// ---- smem layout (bytes) ----
#define OFF_W    0                      // 384*128 f32 swizzled   = 196608
#define OFF_H0   196608                 // 14*128 f32 h buf 0     =   7168
#define OFF_H1   203776                 // 14*128 f32 h buf 1     =   7168
#define OFF_GI   210944                 // 4*384 f32              =   6144
#define OFF_TOK  217088                 // 2 groups x 2 bufs x 8  =     32
#define SMEM_BYTES 217120

// packed fp32x2 FMA (Blackwell)
__device__ __forceinline__ unsigned long long fma2(unsigned long long a,
                                                   unsigned long long b,
                                                   unsigned long long c) {
    unsigned long long d;
    asm("fma.rn.f32x2 %0, %1, %2, %3;" : "=l"(d) : "l"(a), "l"(b), "l"(c));
    return d;
}
__device__ __forceinline__ float reduce2(unsigned long long a) {
    unsigned int lo, hi;
    asm("mov.b64 {%0, %1}, %2;" : "=r"(lo), "=r"(hi) : "l"(a));
    return __uint_as_float(lo) + __uint_as_float(hi);
}
__device__ __forceinline__ float tanh_fast(float x) {
    float y;
    asm("tanh.approx.f32 %0, %1;" : "=f"(y) : "f"(x));
    return y;
}
__device__ __forceinline__ float sigmoid_fast(float x) {
    return fmaf(tanh_fast(0.5f * x), 0.5f, 0.5f);
}
// group barrier: 128 threads (4 aligned warps) of m-group mg
__device__ __forceinline__ void group_bar(int mg) {
    asm volatile("bar.sync %0, 128;" :: "r"(mg + 1) : "memory");
}

__global__ void detect_kernel(const int* __restrict__ x32) {
    int all_zero = 1;
    for (int i = 1; i < 128; i += 2) all_zero &= (x32[i] == 0);
    g_is64 = all_zero;
}

__global__ void tok_kernel(const void* __restrict__ xraw) {
    int i = blockIdx.x * blockDim.x + threadIdx.x;
    if (i >= BB * TT) return;
    int b = i / TT, t = i % TT;
    int v;
    if (g_is64) v = (int)((const long long*)xraw)[i];
    else        v = ((const int*)xraw)[i];
    g_tok[t * BPAD + b] = (unsigned char)v;
}

__global__ void gi_kernel(const float* __restrict__ W_ih,
                          const float* __restrict__ emb,
                          const float* __restrict__ b_ih) {
    int g = threadIdx.x;
    if (g >= G3) return;
    float bi = b_ih[g];
    for (int v = 0; v < VOCAB; ++v) {
        float s = bi;
#pragma unroll 8
        for (int e = 0; e < EE; ++e) s += W_ih[g * EE + e] * emb[v * EE + e];
        g_gi[v * G3 + g] = s;
    }
}

extern __shared__ char smem[];

__global__ __launch_bounds__(NTHR, 1)
void gru_kernel(const float* __restrict__ W_hh, const float* __restrict__ b_hh,
                const float* __restrict__ W_fc, const float* __restrict__ b_fc,
                float* __restrict__ out) {
    float*         h0_s  = (float*)(smem + OFF_H0);
    float*         h1_s  = (float*)(smem + OFF_H1);
    float*         gi_s  = (float*)(smem + OFF_GI);
    unsigned char* tok_s = (unsigned char*)(smem + OFF_TOK);

    const int tid  = threadIdx.x;     // 0..255
    const int j    = tid & 127;       // hidden unit
    const int mg   = tid >> 7;        // m-group: rows GR*mg .. GR*mg+GR-1
    const int m0   = mg * GR;
    const int row0 = blockIdx.x * MROWS;

    // W_hh (gates r,z only needed in smem) -> XOR-swizzled on 16B granules
    {
        float4* W_s4 = (float4*)(smem + OFF_W);
        for (int r = tid; r < 256; r += NTHR) {   // rows 0..255 (r,z gates)
            const float4* Wg = (const float4*)(W_hh + r * HH);
            int swr = r & 7;
#pragma unroll 4
            for (int c = 0; c < 32; ++c) W_s4[r * 32 + (c ^ swr)] = Wg[c];
        }
    }
    for (int i = tid; i < VOCAB * G3; i += NTHR) gi_s[i] = g_gi[i];
    for (int i = tid; i < MROWS * HH; i += NTHR) h0_s[i] = 0.0f;
    // group-local token staging: lane j<GR of group mg owns row m0+j
    if (j < GR) tok_s[mg * 16 + j] = g_tok[0 * BPAD + row0 + m0 + j] & 3;

    // gate-n weight row cached entirely in registers (read gmem once,
    // coalesced-ish 16B per thread; indexed by plain granule c, no swizzle)
    unsigned long long wnr[64];   // 32 granules x {lo,hi} ulonglong
    {
        const ulonglong2* Wg = (const ulonglong2*)(W_hh + (256 + j) * HH);
#pragma unroll
        for (int c = 0; c < 32; ++c) {
            ulonglong2 v = Wg[c];
            wnr[2 * c] = v.x; wnr[2 * c + 1] = v.y;
        }
    }

    const unsigned long long bR = (unsigned long long)__float_as_uint(b_hh[j]);
    const unsigned long long bZ = (unsigned long long)__float_as_uint(b_hh[128 + j]);
    const unsigned long long bN = (unsigned long long)__float_as_uint(b_hh[256 + j]);
    __syncthreads();

    const int sw = j & 7;   // (j+128)&7 == j&7
    const ulonglong2* Wr = (const ulonglong2*)(smem + OFF_W) + (j)       * 32;
    const ulonglong2* Wz = (const ulonglong2*)(smem + OFF_W) + (128 + j) * 32;

    // old-h carried in registers: hreg[m] == h_cur[(m0+m)*HH + j]
    float hreg[GR];
#pragma unroll
    for (int m = 0; m < GR; ++m) hreg[m] = 0.0f;

    for (int t = 0; t < TT; ++t) {
        const int cur = t & 1;
        float* h_cur = cur ? h1_s : h0_s;
        float* h_nxt = cur ? h0_s : h1_s;
        const ulonglong2* hc2 = (const ulonglong2*)h_cur;

        // prefetch next step's tokens for this group's rows
        unsigned char nt = 0;
        if (j < GR && t + 1 < TT)
            nt = g_tok[(t + 1) * BPAD + row0 + m0 + j] & 3;

        // ---- gh = b_hh + h @ W_hh^T for all 3 gates of unit j, GR rows ----
        unsigned long long aR[GR], aZ[GR], aN[GR];
#pragma unroll
        for (int m = 0; m < GR; ++m) { aR[m] = bR; aZ[m] = bZ; aN[m] = bN; }

        // full unroll: wn comes from registers, Wr/Wz from smem
#pragma unroll
        for (int c = 0; c < 32; ++c) {
            const int ci = c ^ sw;
            ulonglong2 wr = Wr[ci];
            ulonglong2 wz = Wz[ci];
            const unsigned long long wn0 = wnr[2 * c], wn1 = wnr[2 * c + 1];
#pragma unroll
            for (int m = 0; m < GR; ++m) {
                ulonglong2 hv = hc2[(m0 + m) * 32 + c];   // warp-broadcast
                aR[m] = fma2(hv.x, wr.x, aR[m]);
                aR[m] = fma2(hv.y, wr.y, aR[m]);
                aZ[m] = fma2(hv.x, wz.x, aZ[m]);
                aZ[m] = fma2(hv.y, wz.y, aZ[m]);
                aN[m] = fma2(hv.x, wn0,  aN[m]);
                aN[m] = fma2(hv.y, wn1,  aN[m]);
            }
        }

        // ---- gates + h update, all thread-local ----
        float sR[GR], sZ[GR], sN[GR];
#pragma unroll
        for (int m = 0; m < GR; ++m) {
            sR[m] = reduce2(aR[m]);
            sZ[m] = reduce2(aZ[m]);
            sN[m] = reduce2(aN[m]);
        }
#pragma unroll
        for (int m = 0; m < GR; ++m) {
            int   v  = tok_s[mg * 16 + cur * 8 + m];
            const float* gv = gi_s + v * G3;
            float r  = sigmoid_fast(gv[j]       + sR[m]);
            float z  = sigmoid_fast(gv[128 + j] + sZ[m]);
            float n  = tanh_fast   (gv[256 + j] + r * sN[m]);
            float hn = fmaf(z, hreg[m] - n, n);           // (1-z)n + z*ho
            hreg[m]  = hn;
            h_nxt[(m0 + m) * HH + j] = hn;
        }
        if (j < GR) tok_s[mg * 16 + (cur ^ 1) * 8 + j] = nt;
        group_bar(mg);
    }

    __syncthreads();   // join groups: logits read all MROWS rows

    // ---- logits = hT @ W_fc.T + b_fc  (final h in buffer 0: TT even) ----
    if (tid < MROWS * VOCAB) {
        int m = tid >> 2, v = tid & 3;
        int row = row0 + m;
        if (row < BB) {
            float        sum = b_fc[v];
            const float* wv  = W_fc + v * HH;
            const float* hr  = h0_s + m * HH;
#pragma unroll 8
            for (int k = 0; k < HH; ++k) sum = fmaf(hr[k], wv[k], sum);
            out[row * VOCAB + v] = sum;
        }
    }
}

extern "C" void kernel_launch(void* const* d_in, const int* in_sizes, int n_in,
                              void* d_out, int out_size) {
    const void*  x    = d_in[0];
    const float* emb  = (const float*)d_in[1];
    const float* W_ih = (const float*)d_in[2];
    const float* W_hh = (const float*)d_in[3];
    const float* b_ih = (const float*)d_in[4];
    const float* b_hh = (const float*)d_in[5];
    const float* W_fc = (const float*)d_in[6];
    const float* b_fc = (const float*)d_in[7];
    float* out = (float*)d_out;

    static int smem_set = 0;
    if (!smem_set) {
        cudaFuncSetAttribute(gru_kernel,
                             cudaFuncAttributeMaxDynamicSharedMemorySize,
                             SMEM_BYTES);
        smem_set = 1;
    }

    detect_kernel<<<1, 1>>>((const int*)x);
    tok_kernel<<<(BB * TT + 255) / 256, 256>>>(x);
    gi_kernel<<<1, G3>>>(W_ih, emb, b_ih);
    gru_kernel<<<NBLK, NTHR, SMEM_BYTES>>>(W_hh, b_hh, W_fc, b_fc, out);
}

// round 10
// speedup vs baseline: 2.4856x; 1.7692x over previous
#include <cuda_runtime.h>
#include <cuda_bf16.h>
#include <cstdint>

#define BB 2048
#define TT 512
#define VOCAB 4
#define EE 64
#define HH 128
#define G3 384
#define NBLK 148
#define MROWS 14
#define BPAD (NBLK * MROWS)
#define NTHR 256
#define GISTR 388      // gi row stride (padded to break bank alignment)

// ---- scratch (no allocs allowed) ----
__device__ float         g_gi[VOCAB * G3];
__device__ unsigned char g_tok[TT * BPAD];   // zero-init => pad rows v=0
__device__ int           g_is64;

// ---- smem layout (bytes) ----
#define OFF_BF   0          // B frags (W hi+lo), 8w*6t*16kt*256B = 196608
#define OFF_AH0  196608     // h-hi buf 0: 16*64 u32 = 4096
#define OFF_AL0  200704     // h-lo buf 0
#define OFF_AH1  204800     // h-hi buf 1
#define OFF_AL1  208896     // h-lo buf 1
#define OFF_GI   212992     // 4*GISTR f32 = 6208
#define OFF_TOK  219200     // 2*16 int = 128
#define SMEM_BYTES 219328

__device__ __forceinline__ float tanh_fast(float x) {
    float y;
    asm("tanh.approx.f32 %0, %1;" : "=f"(y) : "f"(x));
    return y;
}
__device__ __forceinline__ float sigmoid_fast(float x) {
    return fmaf(tanh_fast(0.5f * x), 0.5f, 0.5f);
}
// pack two floats as bf16x2: low half = a (even k), high half = b (odd k)
__device__ __forceinline__ uint32_t pk_bf16(float a, float b) {
    __nv_bfloat16 ha = __float2bfloat16(a), hb = __float2bfloat16(b);
    return (uint32_t)__bfloat16_as_ushort(ha) |
           ((uint32_t)__bfloat16_as_ushort(hb) << 16);
}
__device__ __forceinline__ float bf_res(float x) {   // residual after bf16 round
    return x - __bfloat162float(__float2bfloat16(x));
}
__device__ __forceinline__ void mma_bf16(float c[4], const uint32_t a[4],
                                         uint64_t b) {
    uint32_t b0 = (uint32_t)b, b1 = (uint32_t)(b >> 32);
    asm("mma.sync.aligned.m16n8k16.row.col.f32.bf16.bf16.f32 "
        "{%0,%1,%2,%3}, {%4,%5,%6,%7}, {%8,%9}, {%0,%1,%2,%3};"
        : "+f"(c[0]), "+f"(c[1]), "+f"(c[2]), "+f"(c[3])
        : "r"(a[0]), "r"(a[1]), "r"(a[2]), "r"(a[3]), "r"(b0), "r"(b1));
}

__global__ void detect_kernel(const int* __restrict__ x32) {
    int all_zero = 1;
    for (int i = 1; i < 128; i += 2) all_zero &= (x32[i] == 0);
    g_is64 = all_zero;
}

__global__ void tok_kernel(const void* __restrict__ xraw) {
    int i = blockIdx.x * blockDim.x + threadIdx.x;
    if (i >= BB * TT) return;
    int b = i / TT, t = i % TT;
    int v;
    if (g_is64) v = (int)((const long long*)xraw)[i];
    else        v = ((const int*)xraw)[i];
    g_tok[t * BPAD + b] = (unsigned char)v;
}

__global__ void gi_kernel(const float* __restrict__ W_ih,
                          const float* __restrict__ emb,
                          const float* __restrict__ b_ih) {
    int g = threadIdx.x;
    if (g >= G3) return;
    float bi = b_ih[g];
    for (int v = 0; v < VOCAB; ++v) {
        float s = bi;
#pragma unroll 8
        for (int e = 0; e < EE; ++e) s += W_ih[g * EE + e] * emb[v * EE + e];
        g_gi[v * G3 + g] = s;
    }
}

extern __shared__ char smem[];

__global__ __launch_bounds__(NTHR, 1)
void gru_kernel(const float* __restrict__ W_hh, const float* __restrict__ b_hh,
                const float* __restrict__ W_fc, const float* __restrict__ b_fc,
                float* __restrict__ out) {
    uint64_t* BF    = (uint64_t*)(smem + OFF_BF);
    uint32_t* AHb[2] = {(uint32_t*)(smem + OFF_AH0), (uint32_t*)(smem + OFF_AH1)};
    uint32_t* ALb[2] = {(uint32_t*)(smem + OFF_AL0), (uint32_t*)(smem + OFF_AL1)};
    float*    gi_s  = (float*)(smem + OFF_GI);
    int*      tok_s = (int*)(smem + OFF_TOK);

    const int tid = threadIdx.x;       // 0..255
    const int l   = tid & 31;
    const int w   = tid >> 5;          // warp 0..7: units [16w, 16w+16)
    const int lg  = l >> 2;            // mma group (row)
    const int lt  = l & 3;             // mma thread-in-group (col pair)
    const int swl = lg << 2;           // A swizzle for rows lg / lg+8
    const int row0 = blockIdx.x * MROWS;

    // ---- stage W hi/lo fragments into smem (frag-ordered, one-time) ----
    // entry idx = l + 32*(kt + 16*(tile + 6*warp)); kt 0-7 = W-hi, 8-15 = W-lo
    for (int idx = tid; idx < 24576; idx += NTHR) {
        int ll = idx & 31, kt = (idx >> 5) & 15, tw = idx >> 9;
        int tile = tw % 6, ww = tw / 6;
        int n = (tile >> 1) * 128 + 16 * ww + 8 * (tile & 1) + (ll >> 2);
        int k = (kt & 7) * 16 + (ll & 3) * 2;
        const float* Wn = W_hh + n * HH + k;
        float x0 = Wn[0], x1 = Wn[1], x2 = Wn[8], x3 = Wn[9];
        uint32_t b0, b1;
        if (kt < 8) { b0 = pk_bf16(x0, x1); b1 = pk_bf16(x2, x3); }
        else { b0 = pk_bf16(bf_res(x0), bf_res(x1));
               b1 = pk_bf16(bf_res(x2), bf_res(x3)); }
        BF[idx] = (uint64_t)b0 | ((uint64_t)b1 << 32);
    }
    // zero h buffers (h0 = 0 -> hi=lo=0)
    for (int i = tid; i < 1024; i += NTHR) {
        AHb[0][i] = 0; ALb[0][i] = 0; AHb[1][i] = 0; ALb[1][i] = 0;
    }
    // gi table with padded stride
    for (int i = tid; i < VOCAB * G3; i += NTHR)
        gi_s[(i / G3) * GISTR + (i % G3)] = g_gi[i];
    // tokens
    if (tid < 16) {
        tok_s[tid]      = (tid < MROWS) ? (g_tok[row0 + tid] & 3) : 0;
        tok_s[16 + tid] = 0;
    }
    // per-thread gate biases for C-frag init
    float bias[6][2];
#pragma unroll
    for (int ti = 0; ti < 6; ++ti)
#pragma unroll
        for (int c = 0; c < 2; ++c)
            bias[ti][c] = b_hh[(ti >> 1) * 128 + 16 * w + 8 * (ti & 1)
                               + 2 * lt + c];
    __syncthreads();

    // per-tile B fragment base pointers (stride 512 entries per tile)
    const uint64_t* Bb[6];
#pragma unroll
    for (int ti = 0; ti < 6; ++ti) Bb[ti] = BF + (w * 6 + ti) * 512 + l;

    float hreg[2][2][2];   // [h-half hp][row-half rh][col c], old h values
#pragma unroll
    for (int hp = 0; hp < 2; ++hp)
#pragma unroll
        for (int rh = 0; rh < 2; ++rh) { hreg[hp][rh][0] = 0.f; hreg[hp][rh][1] = 0.f; }

    for (int t = 0; t < TT; ++t) {
        const int cur = t & 1, nxt = cur ^ 1;
        const uint32_t* Ah = AHb[cur];
        const uint32_t* Al = ALb[cur];

        int ntv = 0;
        if (tid < MROWS && t + 1 < TT)
            ntv = g_tok[(t + 1) * BPAD + row0 + tid] & 3;

        // ---- load A fragments (h hi/lo), swizzled, conflict-free ----
        uint32_t Afh[8][4], Afl[8][4];
#pragma unroll
        for (int kc = 0; kc < 8; ++kc) {
            int w0 = kc * 8 + lt;
            int p0 = lg * 64 + (w0 ^ swl);
            int p2 = lg * 64 + ((w0 + 4) ^ swl);
            Afh[kc][0] = Ah[p0];       Afh[kc][1] = Ah[p0 + 512];
            Afh[kc][2] = Ah[p2];       Afh[kc][3] = Ah[p2 + 512];
            Afl[kc][0] = Al[p0];       Afl[kc][1] = Al[p0 + 512];
            Afl[kc][2] = Al[p2];       Afl[kc][3] = Al[p2 + 512];
        }

        // ---- C init with biases ----
        float C[6][4];
#pragma unroll
        for (int ti = 0; ti < 6; ++ti) {
            C[ti][0] = bias[ti][0]; C[ti][1] = bias[ti][1];
            C[ti][2] = bias[ti][0]; C[ti][3] = bias[ti][1];
        }

        // ---- 3-pass split-precision GEMM on tensor pipe ----
        // kt 0-7: A-hi x W-hi; 8-15: A-lo x W-hi; 16-23: A-hi x W-lo
#pragma unroll
        for (int kt = 0; kt < 24; ++kt) {
            const uint32_t* a = (kt < 8)  ? Afh[kt]
                              : (kt < 16) ? Afl[kt - 8]
                                          : Afh[kt - 16];
            const int bk = (kt < 8) ? kt : kt - 8;
#pragma unroll
            for (int ti = 0; ti < 6; ++ti)
                mma_bf16(C[ti], a, Bb[ti][bk * 32]);
        }

        // ---- gates + h update (thread-local via C-frag ownership) ----
        uint32_t* AhN = AHb[nxt];
        uint32_t* AlN = ALb[nxt];
#pragma unroll
        for (int hp = 0; hp < 2; ++hp) {
#pragma unroll
            for (int rh = 0; rh < 2; ++rh) {
                int m = lg + 8 * rh;
                int v = tok_s[cur * 16 + m];
                const float* gv = gi_s + v * GISTR + 16 * w + 8 * hp + 2 * lt;
                float hn01[2];
#pragma unroll
                for (int c = 0; c < 2; ++c) {
                    int  reg = 2 * rh + c;
                    float r = sigmoid_fast(gv[c]       + C[hp][reg]);
                    float z = sigmoid_fast(gv[128 + c] + C[2 + hp][reg]);
                    float n = tanh_fast   (gv[256 + c] + r * C[4 + hp][reg]);
                    float hn = fmaf(z, hreg[hp][rh][c] - n, n);
                    hreg[hp][rh][c] = hn;
                    hn01[c] = hn;
                }
                int word = (8 * w + 4 * hp + lt) ^ swl;   // swizzle f(m&7)=lg
                AhN[m * 64 + word] = pk_bf16(hn01[0], hn01[1]);
                AlN[m * 64 + word] = pk_bf16(bf_res(hn01[0]), bf_res(hn01[1]));
            }
        }
        if (tid < MROWS) tok_s[nxt * 16 + tid] = ntv;
        __syncthreads();
    }

    // ---- final h (fp32, from regs) -> smem (reuse BF region) ----
    float* hf = (float*)(smem + OFF_BF);
#pragma unroll
    for (int hp = 0; hp < 2; ++hp)
#pragma unroll
        for (int rh = 0; rh < 2; ++rh)
#pragma unroll
            for (int c = 0; c < 2; ++c) {
                int m = lg + 8 * rh;
                int u = 16 * w + 8 * hp + 2 * lt + c;
                hf[m * HH + u] = hreg[hp][rh][c];
            }
    __syncthreads();

    // ---- logits = hT @ W_fc.T + b_fc ----
    if (tid < MROWS * VOCAB) {
        int m = tid >> 2, v = tid & 3;
        int row = row0 + m;
        if (row < BB) {
            float        sum = b_fc[v];
            const float* wv  = W_fc + v * HH;
            const float* hr  = hf + m * HH;
#pragma unroll 8
            for (int k = 0; k < HH; ++k) sum = fmaf(hr[k], wv[k], sum);
            out[row * VOCAB + v] = sum;
        }
    }
}

extern "C" void kernel_launch(void* const* d_in, const int* in_sizes, int n_in,
                              void* d_out, int out_size) {
    const void*  x    = d_in[0];
    const float* emb  = (const float*)d_in[1];
    const float* W_ih = (const float*)d_in[2];
    const float* W_hh = (const float*)d_in[3];
    const float* b_ih = (const float*)d_in[4];
    const float* b_hh = (const float*)d_in[5];
    const float* W_fc = (const float*)d_in[6];
    const float* b_fc = (const float*)d_in[7];
    float* out = (float*)d_out;

    static int smem_set = 0;
    if (!smem_set) {
        cudaFuncSetAttribute(gru_kernel,
                             cudaFuncAttributeMaxDynamicSharedMemorySize,
                             SMEM_BYTES);
        smem_set = 1;
    }

    detect_kernel<<<1, 1>>>((const int*)x);
    tok_kernel<<<(BB * TT + 255) / 256, 256>>>(x);
    gi_kernel<<<1, G3>>>(W_ih, emb, b_ih);
    gru_kernel<<<NBLK, NTHR, SMEM_BYTES>>>(W_hh, b_hh, W_fc, b_fc, out);
}

// round 11
// speedup vs baseline: 2.7504x; 1.1066x over previous
#include <cuda_runtime.h>
#include <cuda_bf16.h>
#include <cstdint>

#define BB 2048
#define TT 512
#define VOCAB 4
#define EE 64
#define HH 128
#define G3 384
#define NBLK 148
#define MROWS 14
#define BPAD (NBLK * MROWS)
#define NTHR 256
#define GISTR 388      // gi row stride (padded to break bank alignment)

// ---- scratch (no allocs allowed) ----
__device__ float         g_gi[VOCAB * G3];
__device__ unsigned char g_tok[TT * BPAD];   // zero-init => pad rows v=0
__device__ int           g_is64;

// ---- smem layout (bytes) ----
#define OFF_BF   0          // B frags (W hi+lo), 8w*6t*16kt*256B = 196608
#define OFF_AH0  196608     // h-hi buf 0: 16*64 u32 = 4096
#define OFF_AL0  200704     // h-lo buf 0
#define OFF_AH1  204800     // h-hi buf 1
#define OFF_AL1  208896     // h-lo buf 1
#define OFF_GI   212992     // 4*GISTR f32 = 6208
#define OFF_TOK  219200     // 2*16 int = 128
#define SMEM_BYTES 219328

__device__ __forceinline__ float tanh_fast(float x) {
    float y;
    asm("tanh.approx.f32 %0, %1;" : "=f"(y) : "f"(x));
    return y;
}
__device__ __forceinline__ float sigmoid_fast(float x) {
    return fmaf(tanh_fast(0.5f * x), 0.5f, 0.5f);
}
__device__ __forceinline__ uint32_t pk_bf16(float a, float b) {
    __nv_bfloat16 ha = __float2bfloat16(a), hb = __float2bfloat16(b);
    return (uint32_t)__bfloat16_as_ushort(ha) |
           ((uint32_t)__bfloat16_as_ushort(hb) << 16);
}
__device__ __forceinline__ float bf_res(float x) {   // residual after bf16 round
    return x - __bfloat162float(__float2bfloat16(x));
}
__device__ __forceinline__ void mma_bf16(float c[4], const uint32_t a[4],
                                         uint64_t b) {
    uint32_t b0 = (uint32_t)b, b1 = (uint32_t)(b >> 32);
    asm("mma.sync.aligned.m16n8k16.row.col.f32.bf16.bf16.f32 "
        "{%0,%1,%2,%3}, {%4,%5,%6,%7}, {%8,%9}, {%0,%1,%2,%3};"
        : "+f"(c[0]), "+f"(c[1]), "+f"(c[2]), "+f"(c[3])
        : "r"(a[0]), "r"(a[1]), "r"(a[2]), "r"(a[3]), "r"(b0), "r"(b1));
}

__global__ void detect_kernel(const int* __restrict__ x32) {
    int all_zero = 1;
    for (int i = 1; i < 128; i += 2) all_zero &= (x32[i] == 0);
    g_is64 = all_zero;
}

__global__ void tok_kernel(const void* __restrict__ xraw) {
    int i = blockIdx.x * blockDim.x + threadIdx.x;
    if (i >= BB * TT) return;
    int b = i / TT, t = i % TT;
    int v;
    if (g_is64) v = (int)((const long long*)xraw)[i];
    else        v = ((const int*)xraw)[i];
    g_tok[t * BPAD + b] = (unsigned char)v;
}

__global__ void gi_kernel(const float* __restrict__ W_ih,
                          const float* __restrict__ emb,
                          const float* __restrict__ b_ih) {
    int g = threadIdx.x;
    if (g >= G3) return;
    float bi = b_ih[g];
    for (int v = 0; v < VOCAB; ++v) {
        float s = bi;
#pragma unroll 8
        for (int e = 0; e < EE; ++e) s += W_ih[g * EE + e] * emb[v * EE + e];
        g_gi[v * G3 + g] = s;
    }
}

extern __shared__ char smem[];

__global__ __launch_bounds__(NTHR, 1)
void gru_kernel(const float* __restrict__ W_hh, const float* __restrict__ b_hh,
                const float* __restrict__ W_fc, const float* __restrict__ b_fc,
                float* __restrict__ out) {
    uint64_t* BF     = (uint64_t*)(smem + OFF_BF);
    uint32_t* AHb[2] = {(uint32_t*)(smem + OFF_AH0), (uint32_t*)(smem + OFF_AH1)};
    uint32_t* ALb[2] = {(uint32_t*)(smem + OFF_AL0), (uint32_t*)(smem + OFF_AL1)};
    float*    gi_s   = (float*)(smem + OFF_GI);
    int*      tok_s  = (int*)(smem + OFF_TOK);

    const int tid = threadIdx.x;       // 0..255
    const int l   = tid & 31;
    const int w   = tid >> 5;          // warp 0..7: units [16w, 16w+16)
    const int lg  = l >> 2;            // mma group (row)
    const int lt  = l & 3;             // mma thread-in-group (col pair)
    const int swl = lg << 2;           // A swizzle for rows lg / lg+8
    const int row0 = blockIdx.x * MROWS;

    // ---- stage W hi/lo fragments into smem (frag-ordered, one-time) ----
    // entry idx = l + 32*(kt + 16*(tile + 6*warp)); kt 0-7 = W-hi, 8-15 = W-lo
    for (int idx = tid; idx < 24576; idx += NTHR) {
        int ll = idx & 31, kt = (idx >> 5) & 15, tw = idx >> 9;
        int tile = tw % 6, ww = tw / 6;
        int n = (tile >> 1) * 128 + 16 * ww + 8 * (tile & 1) + (ll >> 2);
        int k = (kt & 7) * 16 + (ll & 3) * 2;
        const float* Wn = W_hh + n * HH + k;
        float x0 = Wn[0], x1 = Wn[1], x2 = Wn[8], x3 = Wn[9];
        uint32_t b0, b1;
        if (kt < 8) { b0 = pk_bf16(x0, x1); b1 = pk_bf16(x2, x3); }
        else { b0 = pk_bf16(bf_res(x0), bf_res(x1));
               b1 = pk_bf16(bf_res(x2), bf_res(x3)); }
        BF[idx] = (uint64_t)b0 | ((uint64_t)b1 << 32);
    }
    for (int i = tid; i < 1024; i += NTHR) {
        AHb[0][i] = 0; ALb[0][i] = 0; AHb[1][i] = 0; ALb[1][i] = 0;
    }
    for (int i = tid; i < VOCAB * G3; i += NTHR)
        gi_s[(i / G3) * GISTR + (i % G3)] = g_gi[i];
    if (tid < 16) {
        tok_s[tid]      = (tid < MROWS) ? (g_tok[row0 + tid] & 3) : 0;
        tok_s[16 + tid] = 0;
    }
    float bias[6][2];
#pragma unroll
    for (int ti = 0; ti < 6; ++ti)
#pragma unroll
        for (int c = 0; c < 2; ++c)
            bias[ti][c] = b_hh[(ti >> 1) * 128 + 16 * w + 8 * (ti & 1)
                               + 2 * lt + c];
    __syncthreads();

    // ---- hoist W-hi fragments into registers (loop-invariant) ----
    uint64_t Whi[48];                       // [ti*8 + kt]
#pragma unroll
    for (int ti = 0; ti < 6; ++ti)
#pragma unroll
        for (int kt = 0; kt < 8; ++kt)
            Whi[ti * 8 + kt] = BF[(w * 6 + ti) * 512 + kt * 32 + l];
    // W-lo stays in smem; per-tile base pointers
    const uint64_t* Blo[6];
#pragma unroll
    for (int ti = 0; ti < 6; ++ti) Blo[ti] = BF + (w * 6 + ti) * 512 + 256 + l;

    float hreg[2][2][2];   // [h-half hp][row-half rh][col c]
#pragma unroll
    for (int hp = 0; hp < 2; ++hp)
#pragma unroll
        for (int rh = 0; rh < 2; ++rh) { hreg[hp][rh][0] = 0.f; hreg[hp][rh][1] = 0.f; }

    for (int t = 0; t < TT; ++t) {
        const int cur = t & 1, nxt = cur ^ 1;
        const uint32_t* Ah = AHb[cur];
        const uint32_t* Al = ALb[cur];

        int ntv = 0;
        if (tid < MROWS && t + 1 < TT)
            ntv = g_tok[(t + 1) * BPAD + row0 + tid] & 3;

        // ---- load A-hi fragments (resident across passes 1 and 3) ----
        uint32_t Afh[8][4];
#pragma unroll
        for (int kc = 0; kc < 8; ++kc) {
            int w0 = kc * 8 + lt;
            int p0 = lg * 64 + (w0 ^ swl);
            int p2 = lg * 64 + ((w0 + 4) ^ swl);
            Afh[kc][0] = Ah[p0];       Afh[kc][1] = Ah[p0 + 512];
            Afh[kc][2] = Ah[p2];       Afh[kc][3] = Ah[p2 + 512];
        }

        float C[6][4];
#pragma unroll
        for (int ti = 0; ti < 6; ++ti) {
            C[ti][0] = bias[ti][0]; C[ti][1] = bias[ti][1];
            C[ti][2] = bias[ti][0]; C[ti][3] = bias[ti][1];
        }

        // ---- pass 1: A-hi x W-hi (B in registers) ----
#pragma unroll
        for (int kt = 0; kt < 8; ++kt)
#pragma unroll
            for (int ti = 0; ti < 6; ++ti)
                mma_bf16(C[ti], Afh[kt], Whi[ti * 8 + kt]);

        // ---- pass 2: A-lo x W-hi (A streamed per k-tile, B in registers) ----
#pragma unroll
        for (int kt = 0; kt < 8; ++kt) {
            uint32_t a[4];
            int w0 = kt * 8 + lt;
            int p0 = lg * 64 + (w0 ^ swl);
            int p2 = lg * 64 + ((w0 + 4) ^ swl);
            a[0] = Al[p0];       a[1] = Al[p0 + 512];
            a[2] = Al[p2];       a[3] = Al[p2 + 512];
#pragma unroll
            for (int ti = 0; ti < 6; ++ti)
                mma_bf16(C[ti], a, Whi[ti * 8 + kt]);
        }

        // ---- pass 3: A-hi x W-lo (B from smem) ----
#pragma unroll
        for (int kt = 0; kt < 8; ++kt)
#pragma unroll
            for (int ti = 0; ti < 6; ++ti)
                mma_bf16(C[ti], Afh[kt], Blo[ti][kt * 32]);

        // ---- gates + h update (thread-local via C-frag ownership) ----
        uint32_t* AhN = AHb[nxt];
        uint32_t* AlN = ALb[nxt];
#pragma unroll
        for (int hp = 0; hp < 2; ++hp) {
#pragma unroll
            for (int rh = 0; rh < 2; ++rh) {
                int m = lg + 8 * rh;
                int v = tok_s[cur * 16 + m];
                const float* gv = gi_s + v * GISTR + 16 * w + 8 * hp + 2 * lt;
                float hn01[2];
#pragma unroll
                for (int c = 0; c < 2; ++c) {
                    int  reg = 2 * rh + c;
                    float r = sigmoid_fast(gv[c]       + C[hp][reg]);
                    float z = sigmoid_fast(gv[128 + c] + C[2 + hp][reg]);
                    float n = tanh_fast   (gv[256 + c] + r * C[4 + hp][reg]);
                    float hn = fmaf(z, hreg[hp][rh][c] - n, n);
                    hreg[hp][rh][c] = hn;
                    hn01[c] = hn;
                }
                int word = (8 * w + 4 * hp + lt) ^ swl;   // swizzle f(m&7)=lg
                AhN[m * 64 + word] = pk_bf16(hn01[0], hn01[1]);
                AlN[m * 64 + word] = pk_bf16(bf_res(hn01[0]), bf_res(hn01[1]));
            }
        }
        if (tid < MROWS) tok_s[nxt * 16 + tid] = ntv;
        __syncthreads();
    }

    // ---- final h (fp32, from regs) -> smem (reuse BF region) ----
    float* hf = (float*)(smem + OFF_BF);
#pragma unroll
    for (int hp = 0; hp < 2; ++hp)
#pragma unroll
        for (int rh = 0; rh < 2; ++rh)
#pragma unroll
            for (int c = 0; c < 2; ++c) {
                int m = lg + 8 * rh;
                int u = 16 * w + 8 * hp + 2 * lt + c;
                hf[m * HH + u] = hreg[hp][rh][c];
            }
    __syncthreads();

    // ---- logits = hT @ W_fc.T + b_fc ----
    if (tid < MROWS * VOCAB) {
        int m = tid >> 2, v = tid & 3;
        int row = row0 + m;
        if (row < BB) {
            float        sum = b_fc[v];
            const float* wv  = W_fc + v * HH;
            const float* hr  = hf + m * HH;
#pragma unroll 8
            for (int k = 0; k < HH; ++k) sum = fmaf(hr[k], wv[k], sum);
            out[row * VOCAB + v] = sum;
        }
    }
}

extern "C" void kernel_launch(void* const* d_in, const int* in_sizes, int n_in,
                              void* d_out, int out_size) {
    const void*  x    = d_in[0];
    const float* emb  = (const float*)d_in[1];
    const float* W_ih = (const float*)d_in[2];
    const float* W_hh = (const float*)d_in[3];
    const float* b_ih = (const float*)d_in[4];
    const float* b_hh = (const float*)d_in[5];
    const float* W_fc = (const float*)d_in[6];
    const float* b_fc = (const float*)d_in[7];
    float* out = (float*)d_out;

    static int smem_set = 0;
    if (!smem_set) {
        cudaFuncSetAttribute(gru_kernel,
                             cudaFuncAttributeMaxDynamicSharedMemorySize,
                             SMEM_BYTES);
        smem_set = 1;
    }

    detect_kernel<<<1, 1>>>((const int*)x);
    tok_kernel<<<(BB * TT + 255) / 256, 256>>>(x);
    gi_kernel<<<1, G3>>>(W_ih, emb, b_ih);
    gru_kernel<<<NBLK, NTHR, SMEM_BYTES>>>(W_hh, b_hh, W_fc, b_fc, out);
}

// round 12
// speedup vs baseline: 2.7830x; 1.0118x over previous
#include <cuda_runtime.h>
#include <cuda_bf16.h>
#include <cstdint>

#define BB 2048
#define TT 512
#define VOCAB 4
#define EE 64
#define HH 128
#define G3 384
#define NBLK 148
#define MROWS 14
#define BPAD (NBLK * MROWS)
#define NTHR 256
#define GISTR 388      // gi row stride (padded to break bank alignment)

// ---- scratch (no allocs allowed) ----
__device__ float         g_gi[VOCAB * G3];   // includes b_ih; +b_hh for gates r,z
__device__ unsigned char g_tok[TT * BPAD];   // zero-init => pad rows v=0
__device__ int           g_is64;

// ---- smem layout (bytes) ----
#define OFF_BF   0          // B frags (W hi+lo), 8w*6t*16kt*256B = 196608
#define OFF_AH0  196608     // h-hi buf 0: 16*64 u32 = 4096
#define OFF_AL0  200704     // h-lo buf 0
#define OFF_AH1  204800     // h-hi buf 1
#define OFF_AL1  208896     // h-lo buf 1
#define OFF_GI   212992     // 4*GISTR f32 = 6208
#define OFF_TOK  219200     // 2*16 int = 128
#define SMEM_BYTES 219328

__device__ __forceinline__ float tanh_fast(float x) {
    float y;
    asm("tanh.approx.f32 %0, %1;" : "=f"(y) : "f"(x));
    return y;
}
__device__ __forceinline__ float sigmoid_fast(float x) {
    return fmaf(tanh_fast(0.5f * x), 0.5f, 0.5f);
}
// pack two f32 -> bf16x2 in one instruction (lo half = a, hi half = b), rn
__device__ __forceinline__ uint32_t pk2(float a, float b) {
    uint32_t r;
    asm("cvt.rn.bf16x2.f32 %0, %1, %2;" : "=r"(r) : "f"(b), "f"(a));
    return r;
}
__device__ __forceinline__ float unpk_lo(uint32_t p) {
    return __bfloat162float(__ushort_as_bfloat16((unsigned short)(p & 0xffffu)));
}
__device__ __forceinline__ float unpk_hi(uint32_t p) {
    return __bfloat162float(__ushort_as_bfloat16((unsigned short)(p >> 16)));
}
__device__ __forceinline__ float bf_res(float x) {   // residual after bf16 round
    return x - __bfloat162float(__float2bfloat16(x));
}
__device__ __forceinline__ void mma_bf16(float c[4], const uint32_t a[4],
                                         uint64_t b) {
    uint32_t b0 = (uint32_t)b, b1 = (uint32_t)(b >> 32);
    asm("mma.sync.aligned.m16n8k16.row.col.f32.bf16.bf16.f32 "
        "{%0,%1,%2,%3}, {%4,%5,%6,%7}, {%8,%9}, {%0,%1,%2,%3};"
        : "+f"(c[0]), "+f"(c[1]), "+f"(c[2]), "+f"(c[3])
        : "r"(a[0]), "r"(a[1]), "r"(a[2]), "r"(a[3]), "r"(b0), "r"(b1));
}

__global__ void detect_kernel(const int* __restrict__ x32) {
    int all_zero = 1;
    for (int i = 1; i < 128; i += 2) all_zero &= (x32[i] == 0);
    g_is64 = all_zero;
}

__global__ void tok_kernel(const void* __restrict__ xraw) {
    int i = blockIdx.x * blockDim.x + threadIdx.x;
    if (i >= BB * TT) return;
    int b = i / TT, t = i % TT;
    int v;
    if (g_is64) v = (int)((const long long*)xraw)[i];
    else        v = ((const int*)xraw)[i];
    g_tok[t * BPAD + b] = (unsigned char)v;
}

// gi[v][g] = b_ih[g] + W_ih[g]·emb[v]  (+ b_hh[g] for gates r,z: g<256)
__global__ void gi_kernel(const float* __restrict__ W_ih,
                          const float* __restrict__ emb,
                          const float* __restrict__ b_ih,
                          const float* __restrict__ b_hh) {
    int g = threadIdx.x;
    if (g >= G3) return;
    float bi = b_ih[g] + (g < 256 ? b_hh[g] : 0.0f);
    for (int v = 0; v < VOCAB; ++v) {
        float s = bi;
#pragma unroll 8
        for (int e = 0; e < EE; ++e) s += W_ih[g * EE + e] * emb[v * EE + e];
        g_gi[v * G3 + g] = s;
    }
}

extern __shared__ char smem[];

__global__ __launch_bounds__(NTHR, 1)
void gru_kernel(const float* __restrict__ W_hh, const float* __restrict__ b_hh,
                const float* __restrict__ W_fc, const float* __restrict__ b_fc,
                float* __restrict__ out) {
    uint64_t* BF     = (uint64_t*)(smem + OFF_BF);
    uint32_t* AHb[2] = {(uint32_t*)(smem + OFF_AH0), (uint32_t*)(smem + OFF_AH1)};
    uint32_t* ALb[2] = {(uint32_t*)(smem + OFF_AL0), (uint32_t*)(smem + OFF_AL1)};
    float*    gi_s   = (float*)(smem + OFF_GI);
    int*      tok_s  = (int*)(smem + OFF_TOK);

    const int tid = threadIdx.x;       // 0..255
    const int l   = tid & 31;
    const int w   = tid >> 5;          // warp 0..7: units [16w, 16w+16)
    const int lg  = l >> 2;            // mma group (row)
    const int lt  = l & 3;             // mma thread-in-group (col pair)
    const int swl = lg << 2;           // A swizzle for rows lg / lg+8
    const int row0 = blockIdx.x * MROWS;

    // ---- stage W hi/lo fragments into smem (frag-ordered, one-time) ----
    for (int idx = tid; idx < 24576; idx += NTHR) {
        int ll = idx & 31, kt = (idx >> 5) & 15, tw = idx >> 9;
        int tile = tw % 6, ww = tw / 6;
        int n = (tile >> 1) * 128 + 16 * ww + 8 * (tile & 1) + (ll >> 2);
        int k = (kt & 7) * 16 + (ll & 3) * 2;
        const float* Wn = W_hh + n * HH + k;
        float x0 = Wn[0], x1 = Wn[1], x2 = Wn[8], x3 = Wn[9];
        uint32_t b0, b1;
        if (kt < 8) { b0 = pk2(x0, x1); b1 = pk2(x2, x3); }
        else { b0 = pk2(bf_res(x0), bf_res(x1));
               b1 = pk2(bf_res(x2), bf_res(x3)); }
        BF[idx] = (uint64_t)b0 | ((uint64_t)b1 << 32);
    }
    for (int i = tid; i < 1024; i += NTHR) {
        AHb[0][i] = 0; ALb[0][i] = 0; AHb[1][i] = 0; ALb[1][i] = 0;
    }
    for (int i = tid; i < VOCAB * G3; i += NTHR)
        gi_s[(i / G3) * GISTR + (i % G3)] = g_gi[i];
    if (tid < 16) {
        tok_s[tid]      = (tid < MROWS) ? (g_tok[row0 + tid] & 3) : 0;
        tok_s[16 + tid] = 0;
    }
    // n-gate bias only (r,z folded into gi table)
    float bN[2][2];
#pragma unroll
    for (int hp = 0; hp < 2; ++hp)
#pragma unroll
        for (int c = 0; c < 2; ++c)
            bN[hp][c] = b_hh[256 + 16 * w + 8 * hp + 2 * lt + c];
    __syncthreads();

    // ---- hoist W-hi fragments into registers (loop-invariant) ----
    uint64_t Whi[48];                       // [ti*8 + kt]
#pragma unroll
    for (int ti = 0; ti < 6; ++ti)
#pragma unroll
        for (int kt = 0; kt < 8; ++kt)
            Whi[ti * 8 + kt] = BF[(w * 6 + ti) * 512 + kt * 32 + l];
    // W-lo stays in smem; per-tile base pointers
    const uint64_t* Blo[6];
#pragma unroll
    for (int ti = 0; ti < 6; ++ti) Blo[ti] = BF + (w * 6 + ti) * 512 + 256 + l;

    float hreg[2][2][2];   // [h-half hp][row-half rh][col c]
#pragma unroll
    for (int hp = 0; hp < 2; ++hp)
#pragma unroll
        for (int rh = 0; rh < 2; ++rh) { hreg[hp][rh][0] = 0.f; hreg[hp][rh][1] = 0.f; }

    for (int t = 0; t < TT; ++t) {
        const int cur = t & 1, nxt = cur ^ 1;
        const uint32_t* Ah = AHb[cur];
        const uint32_t* Al = ALb[cur];

        int ntv = 0;
        if (tid < MROWS && t + 1 < TT)
            ntv = g_tok[(t + 1) * BPAD + row0 + tid] & 3;

        // ---- load ALL A fragments upfront (deep MLP batch) ----
        uint32_t Afh[8][4], Afl[8][4];
#pragma unroll
        for (int kc = 0; kc < 8; ++kc) {
            int w0 = kc * 8 + lt;
            int p0 = lg * 64 + (w0 ^ swl);
            int p2 = lg * 64 + ((w0 + 4) ^ swl);
            Afh[kc][0] = Ah[p0];       Afh[kc][1] = Ah[p0 + 512];
            Afh[kc][2] = Ah[p2];       Afh[kc][3] = Ah[p2 + 512];
            Afl[kc][0] = Al[p0];       Afl[kc][1] = Al[p0 + 512];
            Afl[kc][2] = Al[p2];       Afl[kc][3] = Al[p2 + 512];
        }

        float C[6][4];
#pragma unroll
        for (int ti = 0; ti < 4; ++ti) {       // r,z gates: bias in gi table
            C[ti][0] = 0.f; C[ti][1] = 0.f; C[ti][2] = 0.f; C[ti][3] = 0.f;
        }
#pragma unroll
        for (int hp = 0; hp < 2; ++hp) {       // n gate: bias inside r*( )
            C[4 + hp][0] = bN[hp][0]; C[4 + hp][1] = bN[hp][1];
            C[4 + hp][2] = bN[hp][0]; C[4 + hp][3] = bN[hp][1];
        }

        // ---- pass 1: A-hi x W-hi (all registers) ----
#pragma unroll
        for (int kt = 0; kt < 8; ++kt)
#pragma unroll
            for (int ti = 0; ti < 6; ++ti)
                mma_bf16(C[ti], Afh[kt], Whi[ti * 8 + kt]);

        // ---- pass 2: A-lo x W-hi (all registers) ----
#pragma unroll
        for (int kt = 0; kt < 8; ++kt)
#pragma unroll
            for (int ti = 0; ti < 6; ++ti)
                mma_bf16(C[ti], Afl[kt], Whi[ti * 8 + kt]);

        // ---- pass 3: A-hi x W-lo (B from smem) ----
#pragma unroll
        for (int kt = 0; kt < 8; ++kt)
#pragma unroll
            for (int ti = 0; ti < 6; ++ti)
                mma_bf16(C[ti], Afh[kt], Blo[ti][kt * 32]);

        // ---- gates + h update (thread-local via C-frag ownership) ----
        uint32_t* AhN = AHb[nxt];
        uint32_t* AlN = ALb[nxt];
#pragma unroll
        for (int hp = 0; hp < 2; ++hp) {
#pragma unroll
            for (int rh = 0; rh < 2; ++rh) {
                int m = lg + 8 * rh;
                int v = tok_s[cur * 16 + m];
                const float* gv = gi_s + v * GISTR + 16 * w + 8 * hp + 2 * lt;
                float hn01[2];
#pragma unroll
                for (int c = 0; c < 2; ++c) {
                    int  reg = 2 * rh + c;
                    float r = sigmoid_fast(gv[c]       + C[hp][reg]);
                    float z = sigmoid_fast(gv[128 + c] + C[2 + hp][reg]);
                    float n = tanh_fast   (gv[256 + c] + r * C[4 + hp][reg]);
                    float hn = fmaf(z, hreg[hp][rh][c] - n, n);
                    hreg[hp][rh][c] = hn;
                    hn01[c] = hn;
                }
                uint32_t phi = pk2(hn01[0], hn01[1]);
                uint32_t plo = pk2(hn01[0] - unpk_lo(phi),
                                   hn01[1] - unpk_hi(phi));
                int word = (8 * w + 4 * hp + lt) ^ swl;   // swizzle f(m&7)=lg
                AhN[m * 64 + word] = phi;
                AlN[m * 64 + word] = plo;
            }
        }
        if (tid < MROWS) tok_s[nxt * 16 + tid] = ntv;
        __syncthreads();
    }

    // ---- final h (fp32, from regs) -> smem (reuse BF region) ----
    float* hf = (float*)(smem + OFF_BF);
#pragma unroll
    for (int hp = 0; hp < 2; ++hp)
#pragma unroll
        for (int rh = 0; rh < 2; ++rh)
#pragma unroll
            for (int c = 0; c < 2; ++c) {
                int m = lg + 8 * rh;
                int u = 16 * w + 8 * hp + 2 * lt + c;
                hf[m * HH + u] = hreg[hp][rh][c];
            }
    __syncthreads();

    // ---- logits = hT @ W_fc.T + b_fc ----
    if (tid < MROWS * VOCAB) {
        int m = tid >> 2, v = tid & 3;
        int row = row0 + m;
        if (row < BB) {
            float        sum = b_fc[v];
            const float* wv  = W_fc + v * HH;
            const float* hr  = hf + m * HH;
#pragma unroll 8
            for (int k = 0; k < HH; ++k) sum = fmaf(hr[k], wv[k], sum);
            out[row * VOCAB + v] = sum;
        }
    }
}

extern "C" void kernel_launch(void* const* d_in, const int* in_sizes, int n_in,
                              void* d_out, int out_size) {
    const void*  x    = d_in[0];
    const float* emb  = (const float*)d_in[1];
    const float* W_ih = (const float*)d_in[2];
    const float* W_hh = (const float*)d_in[3];
    const float* b_ih = (const float*)d_in[4];
    const float* b_hh = (const float*)d_in[5];
    const float* W_fc = (const float*)d_in[6];
    const float* b_fc = (const float*)d_in[7];
    float* out = (float*)d_out;

    static int smem_set = 0;
    if (!smem_set) {
        cudaFuncSetAttribute(gru_kernel,
                             cudaFuncAttributeMaxDynamicSharedMemorySize,
                             SMEM_BYTES);
        smem_set = 1;
    }

    detect_kernel<<<1, 1>>>((const int*)x);
    tok_kernel<<<(BB * TT + 255) / 256, 256>>>(x);
    gi_kernel<<<1, G3>>>(W_ih, emb, b_ih, b_hh);
    gru_kernel<<<NBLK, NTHR, SMEM_BYTES>>>(W_hh, b_hh, W_fc, b_fc, out);
}